// round 15
// baseline (speedup 1.0000x reference)
#include <cuda_runtime.h>
#include <cuda_bf16.h>
#include <math.h>
#include <stdint.h>

// ---------------------------------------------------------------------------
// Problem constants (fixed: B=8, L=2048, DM=DH=1024)
// ---------------------------------------------------------------------------
#define BB     8
#define LL     2048
#define DM     1024
#define DH     1024
#define MM     (BB * LL)          // 16384 rows
#define NCHUNK 32
#define CL     (LL / NCHUNK)      // 64
#define NDS    2048               // fused delta|pre output width

// GEMM smem layout (elements) per pipeline stage (block tile 128x128, BK=32):
//   [0,5120)       A_hi tile 128x32, row stride 40
//   [5120,10240)   A_lo tile
//   [10240,15360)  B_hi tile 128x32, row stride 40
//   [15360,20480)  B_lo tile
#define STAGE_ELEMS 20480
#define STAGE_BYTES (STAGE_ELEMS * 2)
#define NSTAGE 3
#define SMEM_BYTES  (NSTAGE * STAGE_BYTES)   // 122880

// ---------------------------------------------------------------------------
// Scratch (__device__ globals; no allocation allowed)
// ---------------------------------------------------------------------------
__device__ __nv_bfloat16 g_xhi [MM * DM];
__device__ __nv_bfloat16 g_xlo [MM * DM];
__device__ __nv_bfloat16 g_Whi [NDS * DM];   // rows 0..1023 = dw, 1024..2047 = Bw
__device__ __nv_bfloat16 g_Wlo [NDS * DM];
__device__ __nv_bfloat16 g_Cwhi[DM * DH];
__device__ __nv_bfloat16 g_Cwlo[DM * DH];
__device__ __nv_bfloat16 g_Dwhi[DM * DM];
__device__ __nv_bfloat16 g_Dwlo[DM * DM];
__device__ float         g_ds  [(size_t)MM * NDS];  // [:,0:1024]=delta, [:,1024:]=pre
__device__ __nv_bfloat16 g_hhi [MM * DH];
__device__ __nv_bfloat16 g_hlo [MM * DH];
__device__ float g_aprod[BB * NCHUNK * DH];
__device__ float g_hend [BB * NCHUNK * DH];
__device__ float g_carry[BB * NCHUNK * DH];

// ---------------------------------------------------------------------------
// Helpers
// ---------------------------------------------------------------------------
__device__ __forceinline__ float softplusf(float v) {
    float av = fabsf(v);
    return fmaxf(v, 0.0f) + log1pf(__expf(-av));
}

__device__ __forceinline__ void ldsm_x4(uint32_t addr, uint32_t& r0, uint32_t& r1,
                                        uint32_t& r2, uint32_t& r3) {
    asm volatile("ldmatrix.sync.aligned.m8n8.x4.shared.b16 {%0,%1,%2,%3}, [%4];"
                 : "=r"(r0), "=r"(r1), "=r"(r2), "=r"(r3) : "r"(addr));
}
__device__ __forceinline__ void mma16816(float* c, const uint32_t* a,
                                         uint32_t b0, uint32_t b1) {
    asm volatile(
        "mma.sync.aligned.m16n8k16.row.col.f32.bf16.bf16.f32 "
        "{%0,%1,%2,%3}, {%4,%5,%6,%7}, {%8,%9}, {%0,%1,%2,%3};"
        : "+f"(c[0]), "+f"(c[1]), "+f"(c[2]), "+f"(c[3])
        : "r"(a[0]), "r"(a[1]), "r"(a[2]), "r"(a[3]), "r"(b0), "r"(b1));
}
__device__ __forceinline__ void cp16(uint32_t dst, const void* src) {
    asm volatile("cp.async.cg.shared.global [%0], [%1], 16;" :: "r"(dst), "l"(src));
}
__device__ __forceinline__ void cp_commit() {
    asm volatile("cp.async.commit_group;");
}
__device__ __forceinline__ void cp_wait1() {
    asm volatile("cp.async.wait_group 1;");
}
__device__ __forceinline__ void cp_wait0() {
    asm volatile("cp.async.wait_group 0;");
}

// ---------------------------------------------------------------------------
// Split kernels (reference device globals directly from device code)
// ---------------------------------------------------------------------------
__global__ __launch_bounds__(256)
void k_split_x(const float* __restrict__ s)
{
    int i = blockIdx.x * blockDim.x + threadIdx.x;
    if (i >= MM * DM) return;
    float v = s[i];
    __nv_bfloat16 h = __float2bfloat16(v);
    g_xhi[i] = h;
    g_xlo[i] = __float2bfloat16(v - __bfloat162float(h));
}

// WHICH: 0 -> dw (W rows 0..1023), 1 -> Bw (W rows 1024..2047), 2 -> Cw, 3 -> Dw
template <int WHICH>
__global__ __launch_bounds__(256)
void k_split_w(const float* __restrict__ s)
{
    int i = blockIdx.x * blockDim.x + threadIdx.x;
    if (i >= DM * DH) return;
    float v = s[i];
    __nv_bfloat16 h = __float2bfloat16(v);
    __nv_bfloat16 l = __float2bfloat16(v - __bfloat162float(h));
    if (WHICH == 0)      { g_Whi[i] = h;           g_Wlo[i] = l; }
    else if (WHICH == 1) { g_Whi[DH * DM + i] = h; g_Wlo[DH * DM + i] = l; }
    else if (WHICH == 2) { g_Cwhi[i] = h;          g_Cwlo[i] = l; }
    else                 { g_Dwhi[i] = h;          g_Dwlo[i] = l; }
}

// ---------------------------------------------------------------------------
// Tensor-core GEMM, fused 3-term split + 3-stage cp.async pipeline
// (CUTLASS-style: one __syncthreads per k-iter, prefetch distance 2,
//  flattened group loop so the grp seam stays pipelined).
// C[M,N] = sum_g (Ahi_g+Alo_g)*(Bhi_g+Blo_g)^T  (dropping lo*lo)  + bias
// Block tile 128(M) x 128(N), BK=32, 256 threads = 8 warps as 2(m) x 4(n),
// warp tile 64x32 = 4(m16) x 4(n8) mma m16n8k16 tiles.
// Both A and B are K-contiguous -> BOTH use non-trans ldmatrix.
// EPI 0: fused delta/pre -> col<DH: softplus(v+db[c]); else v+Bb[c-DH] -> g_ds
// EPI 1: output          -> v + Cb[c] + Db[c]                         -> Cout
// ---------------------------------------------------------------------------
template <int EPI>
__global__ __launch_bounds__(256)
void k_mma(const float* __restrict__ bias0, const float* __restrict__ bias1,
           float* __restrict__ Cout, int N, int K)
{
    constexpr int NG = (EPI == 0) ? 1 : 2;
    const __nv_bfloat16* GAhi[NG];
    const __nv_bfloat16* GAlo[NG];
    const __nv_bfloat16* GBhi[NG];
    const __nv_bfloat16* GBlo[NG];
    if (EPI == 0) {
        GAhi[0] = g_xhi; GAlo[0] = g_xlo; GBhi[0] = g_Whi; GBlo[0] = g_Wlo;
    } else {
        GAhi[0] = g_hhi; GAlo[0] = g_hlo; GBhi[0] = g_Cwhi; GBlo[0] = g_Cwlo;
        GAhi[1] = g_xhi; GAlo[1] = g_xlo; GBhi[1] = g_Dwhi; GBlo[1] = g_Dwlo;
    }
    float* C = (EPI == 0) ? g_ds : Cout;

    extern __shared__ __align__(16) __nv_bfloat16 smem[];

    const int tid  = threadIdx.x;
    const int lane = tid & 31;
    const int warp = tid >> 5;
    const int wm   = warp >> 2;     // 0..1 -> m offset wm*64
    const int wn   = warp & 3;      // 0..3 -> n offset wn*32
    const int bm   = blockIdx.y * 128;
    const int bn   = blockIdx.x * 128;

    float acc[4][4][4];
    #pragma unroll
    for (int i = 0; i < 4; ++i)
        #pragma unroll
        for (int j = 0; j < 4; ++j)
            #pragma unroll
            for (int q = 0; q < 4; ++q) acc[i][j][q] = 0.0f;

    const uint32_t smem_u = (uint32_t)__cvta_generic_to_shared(smem);

    // cp.async load map (16B chunks): rows 0..127 in 2 reps, col (tid&3)*8
    const int ldc = (tid & 3) * 8;

    // ldmatrix x4 address patterns (verified in R7/R13/R14 baselines)
    const int a_r = lane & 15, a_c8 = (lane >> 4) * 8;
    const int b_nrow = (lane & 7) + ((lane >> 3) & 1) * 8;   // mats 0/2: n0-7, 1/3: n8-15
    const int b_kc8  = (lane >> 4) * 8;                      // mats 0/1: k0, 2/3: k8

    const int NT = K / 32;
    const int F  = NG * NT;       // flattened iteration count

    // ---- flat-index stage loader (8 cp.async/thread + commit) ----
    auto load_flat = [&](int f) {
        const int g2 = f / NT;
        const int kt = f % NT;
        const int k0 = kt * 32;
        const __nv_bfloat16* __restrict__ Ahi = GAhi[g2];
        const __nv_bfloat16* __restrict__ Alo = GAlo[g2];
        const __nv_bfloat16* __restrict__ Bhi = GBhi[g2];
        const __nv_bfloat16* __restrict__ Blo = GBlo[g2];
        const uint32_t s0 = smem_u + (uint32_t)(f % NSTAGE) * STAGE_BYTES;
        #pragma unroll
        for (int rep = 0; rep < 2; ++rep) {
            int row = (rep * 256 + tid) >> 2;   // 0..127
            uint32_t doff = (uint32_t)(row * 40 + ldc) * 2;
            cp16(s0 + doff,              Ahi + (size_t)(bm + row) * K + k0 + ldc);
            cp16(s0 +  5120u * 2 + doff, Alo + (size_t)(bm + row) * K + k0 + ldc);
            cp16(s0 + 10240u * 2 + doff, Bhi + (size_t)(bn + row) * K + k0 + ldc);
            cp16(s0 + 15360u * 2 + doff, Blo + (size_t)(bn + row) * K + k0 + ldc);
        }
        cp_commit();
    };

    // prologue: fill 2 stages
    load_flat(0);
    load_flat(1);

    #pragma unroll 1
    for (int f = 0; f < F; ++f) {
        // ensure this thread's group f is complete (leave at most the newest)
        if (f == F - 1) cp_wait0(); else cp_wait1();
        // cross-thread visibility of stage f AND release of stage (f-1)%3 readers
        __syncthreads();
        // prefetch stage f+2 (overwrites stage (f-1)%3 — safe: all threads passed sync)
        if (f + 2 < F) load_flat(f + 2);

        const uint32_t aHiB = smem_u + (uint32_t)(f % NSTAGE) * STAGE_BYTES;
        const uint32_t aLoB = aHiB +  5120u * 2;
        const uint32_t bHiB = aHiB + 10240u * 2;
        const uint32_t bLoB = aHiB + 15360u * 2;

        #pragma unroll
        for (int ks = 0; ks < 2; ++ks) {
            uint32_t ahi[4][4], alo[4][4], bhi[2][4], blo[2][4];
            #pragma unroll
            for (int mt = 0; mt < 4; ++mt) {
                uint32_t off = 2u * (uint32_t)((wm * 64 + mt * 16 + a_r) * 40
                                               + ks * 16 + a_c8);
                ldsm_x4(aHiB + off, ahi[mt][0], ahi[mt][1], ahi[mt][2], ahi[mt][3]);
                ldsm_x4(aLoB + off, alo[mt][0], alo[mt][1], alo[mt][2], alo[mt][3]);
            }
            #pragma unroll
            for (int p2 = 0; p2 < 2; ++p2) {
                uint32_t off = 2u * (uint32_t)((wn * 32 + p2 * 16 + b_nrow) * 40
                                               + ks * 16 + b_kc8);
                ldsm_x4(bHiB + off, bhi[p2][0], bhi[p2][1], bhi[p2][2], bhi[p2][3]);
                ldsm_x4(bLoB + off, blo[p2][0], blo[p2][1], blo[p2][2], blo[p2][3]);
            }
            #pragma unroll
            for (int mt = 0; mt < 4; ++mt)
                #pragma unroll
                for (int p2 = 0; p2 < 2; ++p2) {
                    // n-subtile p2*2+0 -> b regs {mat0,mat2}; p2*2+1 -> {mat1,mat3}
                    mma16816(acc[mt][p2 * 2 + 0], ahi[mt], bhi[p2][0], bhi[p2][2]);
                    mma16816(acc[mt][p2 * 2 + 1], ahi[mt], bhi[p2][1], bhi[p2][3]);
                    mma16816(acc[mt][p2 * 2 + 0], alo[mt], bhi[p2][0], bhi[p2][2]);
                    mma16816(acc[mt][p2 * 2 + 1], alo[mt], bhi[p2][1], bhi[p2][3]);
                    mma16816(acc[mt][p2 * 2 + 0], ahi[mt], blo[p2][0], blo[p2][2]);
                    mma16816(acc[mt][p2 * 2 + 1], ahi[mt], blo[p2][1], blo[p2][3]);
                }
        }
    }

    const int g  = lane >> 2;
    const int tq = lane & 3;
    #pragma unroll
    for (int mt = 0; mt < 4; ++mt) {
        #pragma unroll
        for (int nt = 0; nt < 4; ++nt) {
            int r = bm + wm * 64 + mt * 16 + g;
            int c = bn + wn * 32 + nt * 8 + 2 * tq;
            #pragma unroll
            for (int q = 0; q < 4; ++q) {
                int rr = r + (q >> 1) * 8;
                int cc = c + (q & 1);
                float v = acc[mt][nt][q];
                if (EPI == 0) {
                    if (cc < DH) v = softplusf(v + bias0[cc]);
                    else         v = v + bias1[cc - DH];
                } else {
                    v = v + bias0[cc] + bias1[cc];
                }
                C[(size_t)rr * N + cc] = v;
            }
        }
    }
}

// ---------------------------------------------------------------------------
// Scan pass A: per-(b,chunk,h) local scan -> chunk summaries
// ---------------------------------------------------------------------------
__global__ __launch_bounds__(DH)
void k_scanA(const float* __restrict__ Avec)
{
    const int b = blockIdx.x / NCHUNK;
    const int c = blockIdx.x % NCHUNK;
    const int h = threadIdx.x;
    const float Ah = Avec[h];

    size_t base = (size_t)(b * LL + c * CL) * NDS + h;
    float ap = 1.0f, hv = 0.0f;
    #pragma unroll 4
    for (int i = 0; i < CL; ++i) {
        float d  = g_ds[base + (size_t)i * NDS];
        float pr = g_ds[base + (size_t)i * NDS + DH];
        float a  = __expf(d * Ah);
        hv = fmaf(a, hv, d * pr);
        ap *= a;
    }
    int sid = (b * NCHUNK + c) * DH + h;
    g_aprod[sid] = ap;
    g_hend [sid] = hv;
}

// ---------------------------------------------------------------------------
// Scan pass B: cross-chunk scan per (b,h)
// ---------------------------------------------------------------------------
__global__ __launch_bounds__(256)
void k_scanB()
{
    int t = blockIdx.x * blockDim.x + threadIdx.x;
    if (t >= BB * DH) return;
    int b = t / DH, h = t % DH;
    float carry = 0.0f;
    #pragma unroll
    for (int c = 0; c < NCHUNK; ++c) {
        int sid = (b * NCHUNK + c) * DH + h;
        g_carry[sid] = carry;
        carry = fmaf(g_aprod[sid], carry, g_hend[sid]);
    }
}

// ---------------------------------------------------------------------------
// Scan pass C: redo local scan from carry; emit h as bf16 hi/lo
// ---------------------------------------------------------------------------
__global__ __launch_bounds__(DH)
void k_scanC(const float* __restrict__ Avec)
{
    const int b = blockIdx.x / NCHUNK;
    const int c = blockIdx.x % NCHUNK;
    const int h = threadIdx.x;
    const float Ah = Avec[h];

    size_t base = (size_t)(b * LL + c * CL) * NDS + h;
    float hv = g_carry[(b * NCHUNK + c) * DH + h];
    #pragma unroll 4
    for (int i = 0; i < CL; ++i) {
        float d  = g_ds[base + (size_t)i * NDS];
        float pr = g_ds[base + (size_t)i * NDS + DH];
        float a  = __expf(d * Ah);
        hv = fmaf(a, hv, d * pr);
        size_t oidx = (size_t)(b * LL + c * CL + i) * DH + h;
        __nv_bfloat16 hi = __float2bfloat16(hv);
        g_hhi[oidx] = hi;
        g_hlo[oidx] = __float2bfloat16(hv - __bfloat162float(hi));
    }
}

// ---------------------------------------------------------------------------
// Launch
// ---------------------------------------------------------------------------
extern "C" void kernel_launch(void* const* d_in, const int* in_sizes, int n_in,
                              void* d_out, int out_size)
{
    const float* x  = (const float*)d_in[0];
    const float* A  = (const float*)d_in[1];
    const float* Bw = (const float*)d_in[2];
    const float* Bb = (const float*)d_in[3];
    const float* Cw = (const float*)d_in[4];
    const float* Cb = (const float*)d_in[5];
    const float* Dw = (const float*)d_in[6];
    const float* Db = (const float*)d_in[7];
    const float* dw = (const float*)d_in[8];
    const float* db = (const float*)d_in[9];
    float* out = (float*)d_out;

    // opt-in to >48KB dynamic smem (attribute set, not an allocation; idempotent)
    cudaFuncSetAttribute(k_mma<0>, cudaFuncAttributeMaxDynamicSharedMemorySize, SMEM_BYTES);
    cudaFuncSetAttribute(k_mma<1>, cudaFuncAttributeMaxDynamicSharedMemorySize, SMEM_BYTES);

    const int nx = MM * DM;
    const int nw = DM * DH;
    k_split_x<<<(nx + 255) / 256, 256>>>(x);
    k_split_w<0><<<(nw + 255) / 256, 256>>>(dw);
    k_split_w<1><<<(nw + 255) / 256, 256>>>(Bw);
    k_split_w<2><<<(nw + 255) / 256, 256>>>(Cw);
    k_split_w<3><<<(nw + 255) / 256, 256>>>(Dw);

    k_mma<0><<<dim3(NDS / 128, MM / 128), 256, SMEM_BYTES>>>(db, Bb, nullptr, NDS, DM);

    k_scanA<<<BB * NCHUNK, DH>>>(A);
    k_scanB<<<(BB * DH + 255) / 256, 256>>>();
    k_scanC<<<BB * NCHUNK, DH>>>(A);

    k_mma<1><<<dim3(DM / 128, MM / 128), 256, SMEM_BYTES>>>(Cb, Db, out, DM, DH);
}

// round 16
// speedup vs baseline: 1.2141x; 1.2141x over previous
#include <cuda_runtime.h>
#include <cuda_bf16.h>
#include <math.h>
#include <stdint.h>

// ---------------------------------------------------------------------------
// Problem constants (fixed: B=8, L=2048, DM=DH=1024)
// ---------------------------------------------------------------------------
#define BB     8
#define LL     2048
#define DM     1024
#define DH     1024
#define MM     (BB * LL)          // 16384 rows
#define NCHUNK 32
#define CL     (LL / NCHUNK)      // 64
#define NDS    2048               // fused delta|pre output width

// GEMM smem layout (elements) per pipeline stage (block tile 128x128, BK=32):
//   [0,5120)       A_hi tile 128x32, row stride 40
//   [5120,10240)   A_lo tile
//   [10240,15360)  B_hi tile 128x32, row stride 40
//   [15360,20480)  B_lo tile
#define STAGE_ELEMS 20480
#define STAGE_BYTES (STAGE_ELEMS * 2)
#define NSTAGE 2
#define SMEM_BYTES  (NSTAGE * STAGE_BYTES)   // 81920 -> 2 CTAs/SM

// ---------------------------------------------------------------------------
// Scratch (__device__ globals; no allocation allowed)
// ---------------------------------------------------------------------------
__device__ __nv_bfloat16 g_xhi [MM * DM];
__device__ __nv_bfloat16 g_xlo [MM * DM];
__device__ __nv_bfloat16 g_Whi [NDS * DM];   // rows 0..1023 = dw, 1024..2047 = Bw
__device__ __nv_bfloat16 g_Wlo [NDS * DM];
__device__ __nv_bfloat16 g_Cwhi[DM * DH];
__device__ __nv_bfloat16 g_Cwlo[DM * DH];
__device__ __nv_bfloat16 g_Dwhi[DM * DM];
__device__ __nv_bfloat16 g_Dwlo[DM * DM];
__device__ float         g_ds  [(size_t)MM * NDS];  // [:,0:1024]=delta, [:,1024:]=pre
__device__ __nv_bfloat16 g_hhi [MM * DH];
__device__ __nv_bfloat16 g_hlo [MM * DH];
__device__ float g_aprod[BB * NCHUNK * DH];
__device__ float g_hend [BB * NCHUNK * DH];
__device__ float g_carry[BB * NCHUNK * DH];

// ---------------------------------------------------------------------------
// Helpers
// ---------------------------------------------------------------------------
__device__ __forceinline__ float softplusf(float v) {
    float av = fabsf(v);
    return fmaxf(v, 0.0f) + log1pf(__expf(-av));
}

__device__ __forceinline__ void ldsm_x4(uint32_t addr, uint32_t& r0, uint32_t& r1,
                                        uint32_t& r2, uint32_t& r3) {
    asm volatile("ldmatrix.sync.aligned.m8n8.x4.shared.b16 {%0,%1,%2,%3}, [%4];"
                 : "=r"(r0), "=r"(r1), "=r"(r2), "=r"(r3) : "r"(addr));
}
__device__ __forceinline__ void mma16816(float* c, const uint32_t* a,
                                         uint32_t b0, uint32_t b1) {
    asm volatile(
        "mma.sync.aligned.m16n8k16.row.col.f32.bf16.bf16.f32 "
        "{%0,%1,%2,%3}, {%4,%5,%6,%7}, {%8,%9}, {%0,%1,%2,%3};"
        : "+f"(c[0]), "+f"(c[1]), "+f"(c[2]), "+f"(c[3])
        : "r"(a[0]), "r"(a[1]), "r"(a[2]), "r"(a[3]), "r"(b0), "r"(b1));
}
__device__ __forceinline__ void cp16(uint32_t dst, const void* src) {
    asm volatile("cp.async.cg.shared.global [%0], [%1], 16;" :: "r"(dst), "l"(src));
}
__device__ __forceinline__ void cp_commit() {
    asm volatile("cp.async.commit_group;");
}
__device__ __forceinline__ void cp_wait0() {
    asm volatile("cp.async.wait_group 0;");
}

// ---------------------------------------------------------------------------
// Split kernels (reference device globals directly from device code)
// ---------------------------------------------------------------------------
__global__ __launch_bounds__(256)
void k_split_x(const float* __restrict__ s)
{
    int i = blockIdx.x * blockDim.x + threadIdx.x;
    if (i >= MM * DM) return;
    float v = s[i];
    __nv_bfloat16 h = __float2bfloat16(v);
    g_xhi[i] = h;
    g_xlo[i] = __float2bfloat16(v - __bfloat162float(h));
}

// WHICH: 0 -> dw (W rows 0..1023), 1 -> Bw (W rows 1024..2047), 2 -> Cw, 3 -> Dw
template <int WHICH>
__global__ __launch_bounds__(256)
void k_split_w(const float* __restrict__ s)
{
    int i = blockIdx.x * blockDim.x + threadIdx.x;
    if (i >= DM * DH) return;
    float v = s[i];
    __nv_bfloat16 h = __float2bfloat16(v);
    __nv_bfloat16 l = __float2bfloat16(v - __bfloat162float(h));
    if (WHICH == 0)      { g_Whi[i] = h;           g_Wlo[i] = l; }
    else if (WHICH == 1) { g_Whi[DH * DM + i] = h; g_Wlo[DH * DM + i] = l; }
    else if (WHICH == 2) { g_Cwhi[i] = h;          g_Cwlo[i] = l; }
    else                 { g_Dwhi[i] = h;          g_Dwlo[i] = l; }
}

// ---------------------------------------------------------------------------
// Tensor-core GEMM, fused 3-term split + 2-stage cp.async pipeline,
// single __syncthreads per k-iter (wait0 -> sync -> prefetch -> compute),
// flattened group loop so the EPI-1 grp seam stays pipelined.
// C[M,N] = sum_g (Ahi_g+Alo_g)*(Bhi_g+Blo_g)^T  (dropping lo*lo)  + bias
// Block tile 128(M) x 128(N), BK=32, 256 threads = 8 warps as 2(m) x 4(n),
// warp tile 64x32 = 4(m16) x 4(n8) mma m16n8k16 tiles.
// Both A and B are K-contiguous -> BOTH use non-trans ldmatrix.
// EPI 0: fused delta/pre -> col<DH: softplus(v+db[c]); else v+Bb[c-DH] -> g_ds
// EPI 1: output          -> v + Cb[c] + Db[c]                         -> Cout
// ---------------------------------------------------------------------------
template <int EPI>
__global__ __launch_bounds__(256)
void k_mma(const float* __restrict__ bias0, const float* __restrict__ bias1,
           float* __restrict__ Cout, int N, int K)
{
    constexpr int NG = (EPI == 0) ? 1 : 2;
    const __nv_bfloat16* GAhi[NG];
    const __nv_bfloat16* GAlo[NG];
    const __nv_bfloat16* GBhi[NG];
    const __nv_bfloat16* GBlo[NG];
    if (EPI == 0) {
        GAhi[0] = g_xhi; GAlo[0] = g_xlo; GBhi[0] = g_Whi; GBlo[0] = g_Wlo;
    } else {
        GAhi[0] = g_hhi; GAlo[0] = g_hlo; GBhi[0] = g_Cwhi; GBlo[0] = g_Cwlo;
        GAhi[1] = g_xhi; GAlo[1] = g_xlo; GBhi[1] = g_Dwhi; GBlo[1] = g_Dwlo;
    }
    float* C = (EPI == 0) ? g_ds : Cout;

    extern __shared__ __align__(16) __nv_bfloat16 smem[];

    const int tid  = threadIdx.x;
    const int lane = tid & 31;
    const int warp = tid >> 5;
    const int wm   = warp >> 2;     // 0..1 -> m offset wm*64
    const int wn   = warp & 3;      // 0..3 -> n offset wn*32
    const int bm   = blockIdx.y * 128;
    const int bn   = blockIdx.x * 128;

    float acc[4][4][4];
    #pragma unroll
    for (int i = 0; i < 4; ++i)
        #pragma unroll
        for (int j = 0; j < 4; ++j)
            #pragma unroll
            for (int q = 0; q < 4; ++q) acc[i][j][q] = 0.0f;

    const uint32_t smem_u = (uint32_t)__cvta_generic_to_shared(smem);

    // cp.async load map (16B chunks): rows 0..127 in 2 reps, col (tid&3)*8
    const int ldc = (tid & 3) * 8;

    // ldmatrix x4 address patterns (verified in R7/R13/R14 baselines)
    const int a_r = lane & 15, a_c8 = (lane >> 4) * 8;
    const int b_nrow = (lane & 7) + ((lane >> 3) & 1) * 8;   // mats 0/2: n0-7, 1/3: n8-15
    const int b_kc8  = (lane >> 4) * 8;                      // mats 0/1: k0, 2/3: k8

    const int NT = K / 32;
    const int F  = NG * NT;       // flattened iteration count

    // ---- flat-index stage loader (8 cp.async/thread + commit) ----
    auto load_flat = [&](int f) {
        const int g2 = f / NT;
        const int kt = f % NT;
        const int k0 = kt * 32;
        const __nv_bfloat16* __restrict__ Ahi = GAhi[g2];
        const __nv_bfloat16* __restrict__ Alo = GAlo[g2];
        const __nv_bfloat16* __restrict__ Bhi = GBhi[g2];
        const __nv_bfloat16* __restrict__ Blo = GBlo[g2];
        const uint32_t s0 = smem_u + (uint32_t)(f & 1) * STAGE_BYTES;
        #pragma unroll
        for (int rep = 0; rep < 2; ++rep) {
            int row = (rep * 256 + tid) >> 2;   // 0..127
            uint32_t doff = (uint32_t)(row * 40 + ldc) * 2;
            cp16(s0 + doff,              Ahi + (size_t)(bm + row) * K + k0 + ldc);
            cp16(s0 +  5120u * 2 + doff, Alo + (size_t)(bm + row) * K + k0 + ldc);
            cp16(s0 + 10240u * 2 + doff, Bhi + (size_t)(bn + row) * K + k0 + ldc);
            cp16(s0 + 15360u * 2 + doff, Blo + (size_t)(bn + row) * K + k0 + ldc);
        }
        cp_commit();
    };

    load_flat(0);   // prologue

    #pragma unroll 1
    for (int f = 0; f < F; ++f) {
        // drain this thread's outstanding loads (group f, issued last iter)
        cp_wait0();
        // all threads: stage f complete+visible; all finished compute f-1
        __syncthreads();
        // prefetch f+1 into stage (f+1)&1 — readers of that stage (compute f-1)
        // are all past the sync above, so overwrite is safe
        if (f + 1 < F) load_flat(f + 1);

        const uint32_t aHiB = smem_u + (uint32_t)(f & 1) * STAGE_BYTES;
        const uint32_t aLoB = aHiB +  5120u * 2;
        const uint32_t bHiB = aHiB + 10240u * 2;
        const uint32_t bLoB = aHiB + 15360u * 2;

        #pragma unroll
        for (int ks = 0; ks < 2; ++ks) {
            uint32_t ahi[4][4], alo[4][4], bhi[2][4], blo[2][4];
            #pragma unroll
            for (int mt = 0; mt < 4; ++mt) {
                uint32_t off = 2u * (uint32_t)((wm * 64 + mt * 16 + a_r) * 40
                                               + ks * 16 + a_c8);
                ldsm_x4(aHiB + off, ahi[mt][0], ahi[mt][1], ahi[mt][2], ahi[mt][3]);
                ldsm_x4(aLoB + off, alo[mt][0], alo[mt][1], alo[mt][2], alo[mt][3]);
            }
            #pragma unroll
            for (int p2 = 0; p2 < 2; ++p2) {
                uint32_t off = 2u * (uint32_t)((wn * 32 + p2 * 16 + b_nrow) * 40
                                               + ks * 16 + b_kc8);
                ldsm_x4(bHiB + off, bhi[p2][0], bhi[p2][1], bhi[p2][2], bhi[p2][3]);
                ldsm_x4(bLoB + off, blo[p2][0], blo[p2][1], blo[p2][2], blo[p2][3]);
            }
            #pragma unroll
            for (int mt = 0; mt < 4; ++mt)
                #pragma unroll
                for (int p2 = 0; p2 < 2; ++p2) {
                    // n-subtile p2*2+0 -> b regs {mat0,mat2}; p2*2+1 -> {mat1,mat3}
                    mma16816(acc[mt][p2 * 2 + 0], ahi[mt], bhi[p2][0], bhi[p2][2]);
                    mma16816(acc[mt][p2 * 2 + 1], ahi[mt], bhi[p2][1], bhi[p2][3]);
                    mma16816(acc[mt][p2 * 2 + 0], alo[mt], bhi[p2][0], bhi[p2][2]);
                    mma16816(acc[mt][p2 * 2 + 1], alo[mt], bhi[p2][1], bhi[p2][3]);
                    mma16816(acc[mt][p2 * 2 + 0], ahi[mt], blo[p2][0], blo[p2][2]);
                    mma16816(acc[mt][p2 * 2 + 1], ahi[mt], blo[p2][1], blo[p2][3]);
                }
        }
    }

    const int g  = lane >> 2;
    const int tq = lane & 3;
    #pragma unroll
    for (int mt = 0; mt < 4; ++mt) {
        #pragma unroll
        for (int nt = 0; nt < 4; ++nt) {
            int r = bm + wm * 64 + mt * 16 + g;
            int c = bn + wn * 32 + nt * 8 + 2 * tq;
            #pragma unroll
            for (int q = 0; q < 4; ++q) {
                int rr = r + (q >> 1) * 8;
                int cc = c + (q & 1);
                float v = acc[mt][nt][q];
                if (EPI == 0) {
                    if (cc < DH) v = softplusf(v + bias0[cc]);
                    else         v = v + bias1[cc - DH];
                } else {
                    v = v + bias0[cc] + bias1[cc];
                }
                C[(size_t)rr * N + cc] = v;
            }
        }
    }
}

// ---------------------------------------------------------------------------
// Scan pass A: per-(b,chunk,h) local scan -> chunk summaries
// ---------------------------------------------------------------------------
__global__ __launch_bounds__(DH)
void k_scanA(const float* __restrict__ Avec)
{
    const int b = blockIdx.x / NCHUNK;
    const int c = blockIdx.x % NCHUNK;
    const int h = threadIdx.x;
    const float Ah = Avec[h];

    size_t base = (size_t)(b * LL + c * CL) * NDS + h;
    float ap = 1.0f, hv = 0.0f;
    #pragma unroll 4
    for (int i = 0; i < CL; ++i) {
        float d  = g_ds[base + (size_t)i * NDS];
        float pr = g_ds[base + (size_t)i * NDS + DH];
        float a  = __expf(d * Ah);
        hv = fmaf(a, hv, d * pr);
        ap *= a;
    }
    int sid = (b * NCHUNK + c) * DH + h;
    g_aprod[sid] = ap;
    g_hend [sid] = hv;
}

// ---------------------------------------------------------------------------
// Scan pass B: cross-chunk scan per (b,h)
// ---------------------------------------------------------------------------
__global__ __launch_bounds__(256)
void k_scanB()
{
    int t = blockIdx.x * blockDim.x + threadIdx.x;
    if (t >= BB * DH) return;
    int b = t / DH, h = t % DH;
    float carry = 0.0f;
    #pragma unroll
    for (int c = 0; c < NCHUNK; ++c) {
        int sid = (b * NCHUNK + c) * DH + h;
        g_carry[sid] = carry;
        carry = fmaf(g_aprod[sid], carry, g_hend[sid]);
    }
}

// ---------------------------------------------------------------------------
// Scan pass C: redo local scan from carry; emit h as bf16 hi/lo
// ---------------------------------------------------------------------------
__global__ __launch_bounds__(DH)
void k_scanC(const float* __restrict__ Avec)
{
    const int b = blockIdx.x / NCHUNK;
    const int c = blockIdx.x % NCHUNK;
    const int h = threadIdx.x;
    const float Ah = Avec[h];

    size_t base = (size_t)(b * LL + c * CL) * NDS + h;
    float hv = g_carry[(b * NCHUNK + c) * DH + h];
    #pragma unroll 4
    for (int i = 0; i < CL; ++i) {
        float d  = g_ds[base + (size_t)i * NDS];
        float pr = g_ds[base + (size_t)i * NDS + DH];
        float a  = __expf(d * Ah);
        hv = fmaf(a, hv, d * pr);
        size_t oidx = (size_t)(b * LL + c * CL + i) * DH + h;
        __nv_bfloat16 hi = __float2bfloat16(hv);
        g_hhi[oidx] = hi;
        g_hlo[oidx] = __float2bfloat16(hv - __bfloat162float(hi));
    }
}

// ---------------------------------------------------------------------------
// Launch
// ---------------------------------------------------------------------------
extern "C" void kernel_launch(void* const* d_in, const int* in_sizes, int n_in,
                              void* d_out, int out_size)
{
    const float* x  = (const float*)d_in[0];
    const float* A  = (const float*)d_in[1];
    const float* Bw = (const float*)d_in[2];
    const float* Bb = (const float*)d_in[3];
    const float* Cw = (const float*)d_in[4];
    const float* Cb = (const float*)d_in[5];
    const float* Dw = (const float*)d_in[6];
    const float* Db = (const float*)d_in[7];
    const float* dw = (const float*)d_in[8];
    const float* db = (const float*)d_in[9];
    float* out = (float*)d_out;

    // opt-in to >48KB dynamic smem (attribute set, not an allocation; idempotent)
    cudaFuncSetAttribute(k_mma<0>, cudaFuncAttributeMaxDynamicSharedMemorySize, SMEM_BYTES);
    cudaFuncSetAttribute(k_mma<1>, cudaFuncAttributeMaxDynamicSharedMemorySize, SMEM_BYTES);

    const int nx = MM * DM;
    const int nw = DM * DH;
    k_split_x<<<(nx + 255) / 256, 256>>>(x);
    k_split_w<0><<<(nw + 255) / 256, 256>>>(dw);
    k_split_w<1><<<(nw + 255) / 256, 256>>>(Bw);
    k_split_w<2><<<(nw + 255) / 256, 256>>>(Cw);
    k_split_w<3><<<(nw + 255) / 256, 256>>>(Dw);

    k_mma<0><<<dim3(NDS / 128, MM / 128), 256, SMEM_BYTES>>>(db, Bb, nullptr, NDS, DM);

    k_scanA<<<BB * NCHUNK, DH>>>(A);
    k_scanB<<<(BB * DH + 255) / 256, 256>>>();
    k_scanC<<<BB * NCHUNK, DH>>>(A);

    k_mma<1><<<dim3(DM / 128, MM / 128), 256, SMEM_BYTES>>>(Cb, Db, out, DM, DH);
}